// round 1
// baseline (speedup 1.0000x reference)
#include <cuda_runtime.h>
#include <math.h>
#include <float.h>

#define BB    4
#define LL    2048
#define EE    512
#define HH    8
#define DD    64
#define UU    40
#define NTOP  40
#define BH    32
#define NROWS 8192
#define PCH   32

__device__ float g_q[BH*LL*DD];
__device__ float g_k[BH*LL*DD];
__device__ float g_v[BH*LL*DD];
__device__ float g_M[BH*LL];
__device__ int   g_top[BH*NTOP];
__device__ float g_es[(size_t)BH*NTOP*LL];
__device__ float g_den[BH*NTOP];
__device__ float g_pupd[(size_t)PCH*BH*NTOP*DD];
__device__ float g_upd[BH*NTOP*DD];
__device__ float g_vmean[BH*DD];
__device__ float g_base[BB*EE];

__device__ __forceinline__ unsigned long long pack2(float x, float y) {
    unsigned long long r;
    asm("mov.b64 %0, {%1, %2};" : "=l"(r) : "f"(x), "f"(y));
    return r;
}
__device__ __forceinline__ void unpack2(unsigned long long v, float& lo, float& hi) {
    asm("mov.b64 {%0, %1}, %2;" : "=f"(lo), "=f"(hi) : "l"(v));
}
__device__ __forceinline__ void fma2(unsigned long long& d, unsigned long long a, unsigned long long b) {
    asm("fma.rn.f32x2 %0, %1, %2, %0;" : "+l"(d) : "l"(a), "l"(b));
}

__global__ __launch_bounds__(256) void proj_gemm(
    const float* __restrict__ Xq, const float* __restrict__ Xk, const float* __restrict__ Xv,
    const float* __restrict__ Wq, const float* __restrict__ Wk, const float* __restrict__ Wv,
    const float* __restrict__ bq, const float* __restrict__ bk, const float* __restrict__ bv)
{
    const float *X, *W, *bias; float* out;
    int z = blockIdx.z;
    if (z == 0)      { X = Xq; W = Wq; bias = bq; out = g_q; }
    else if (z == 1) { X = Xk; W = Wk; bias = bk; out = g_k; }
    else             { X = Xv; W = Wv; bias = bv; out = g_v; }

    __shared__ float As[16][128];
    __shared__ float Bs[16][128];

    int m0 = blockIdx.x * 128;
    int n0 = blockIdx.y * 128;
    int tid = threadIdx.x;
    int tn = tid & 15, tm = tid >> 4;

    unsigned long long acc2[8][4];
    #pragma unroll
    for (int i = 0; i < 8; i++)
        #pragma unroll
        for (int j = 0; j < 4; j++) acc2[i][j] = 0ull;

    for (int k0 = 0; k0 < EE; k0 += 16) {
        #pragma unroll
        for (int it = 0; it < 2; it++) {
            int f  = tid + it * 256;
            int r  = f >> 2;
            int c4 = f & 3;
            float4 va = *(const float4*)&X[(size_t)(m0 + r) * EE + k0 + c4 * 4];
            As[c4*4+0][r] = va.x; As[c4*4+1][r] = va.y;
            As[c4*4+2][r] = va.z; As[c4*4+3][r] = va.w;
            float4 vb = *(const float4*)&W[(size_t)(n0 + r) * EE + k0 + c4 * 4];
            Bs[c4*4+0][r] = vb.x; Bs[c4*4+1][r] = vb.y;
            Bs[c4*4+2][r] = vb.z; Bs[c4*4+3][r] = vb.w;
        }
        __syncthreads();
        #pragma unroll
        for (int kk = 0; kk < 16; kk++) {
            float a[8];
            *(float4*)&a[0] = *(const float4*)&As[kk][tm*8];
            *(float4*)&a[4] = *(const float4*)&As[kk][tm*8 + 4];
            unsigned long long bp[4];
            #pragma unroll
            for (int j = 0; j < 4; j++)
                bp[j] = *(const unsigned long long*)&Bs[kk][tn*8 + j*2];
            #pragma unroll
            for (int i = 0; i < 8; i++) {
                unsigned long long aa = pack2(a[i], a[i]);
                #pragma unroll
                for (int j = 0; j < 4; j++) fma2(acc2[i][j], aa, bp[j]);
            }
        }
        __syncthreads();
    }

    int c0 = n0 + tn * 8;
    int h  = c0 >> 6;
    int d0 = c0 & 63;
    float4 bia0 = *(const float4*)&bias[c0];
    float4 bia1 = *(const float4*)&bias[c0 + 4];
    #pragma unroll
    for (int i = 0; i < 8; i++) {
        int row = m0 + tm * 8 + i;
        int bb  = row >> 11, l = row & 2047;
        float r0, r1, r2, r3, r4, r5, r6, r7;
        unpack2(acc2[i][0], r0, r1);
        unpack2(acc2[i][1], r2, r3);
        unpack2(acc2[i][2], r4, r5);
        unpack2(acc2[i][3], r6, r7);
        float4 o0 = { r0 + bia0.x, r1 + bia0.y, r2 + bia0.z, r3 + bia0.w };
        float4 o1 = { r4 + bia1.x, r5 + bia1.y, r6 + bia1.z, r7 + bia1.w };
        float* dst = out + (((size_t)bb * HH + h) * LL + l) * DD + d0;
        *(float4*)&dst[0] = o0;
        *(float4*)&dst[4] = o1;
    }
}

__global__ __launch_bounds__(256) void qk_sample_kernel(const int* __restrict__ idxs) {
    int gw   = blockIdx.x * 8 + (threadIdx.x >> 5);
    int lane = threadIdx.x & 31;
    int bh = gw >> 11, l = gw & 2047;
    const float* qrow = g_q + ((size_t)bh * LL + l) * DD;
    float2 qv = *(const float2*)&qrow[lane * 2];
    const float* kbase = g_k + (size_t)bh * LL * DD;
    float smax = -FLT_MAX, ssum = 0.f;
    for (int s = 0; s < UU; s++) {
        int ki = idxs[l * UU + s];
        float2 kv = *(const float2*)&kbase[(size_t)ki * DD + lane * 2];
        float p = qv.x * kv.x + qv.y * kv.y;
        #pragma unroll
        for (int off = 16; off; off >>= 1) p += __shfl_xor_sync(0xffffffffu, p, off);
        smax = fmaxf(smax, p);
        ssum += p;
    }
    if (lane == 0) g_M[gw] = smax - ssum * (1.0f / LL);
}

__global__ __launch_bounds__(256) void topk_kernel() {
    __shared__ float vals[LL];
    __shared__ float rv[256];
    __shared__ int   ri[256];
    int bh = blockIdx.x, t = threadIdx.x;
    for (int i = t; i < LL; i += 256) vals[i] = g_M[bh * LL + i];
    __syncthreads();
    for (int it = 0; it < NTOP; it++) {
        float bv = -FLT_MAX; int bi = 0x7fffffff;
        for (int i = t; i < LL; i += 256) {
            float v = vals[i];
            if (v > bv || (v == bv && i < bi)) { bv = v; bi = i; }
        }
        rv[t] = bv; ri[t] = bi;
        __syncthreads();
        for (int s = 128; s > 0; s >>= 1) {
            if (t < s) {
                float ov = rv[t + s]; int oi = ri[t + s];
                if (ov > rv[t] || (ov == rv[t] && oi < ri[t])) { rv[t] = ov; ri[t] = oi; }
            }
            __syncthreads();
        }
        if (t == 0) { g_top[bh * NTOP + it] = ri[0]; vals[ri[0]] = -FLT_MAX; }
        __syncthreads();
    }
}

#define KST 132
__global__ __launch_bounds__(256) void scores_kernel() {
    __shared__ float qs[NTOP * DD];
    __shared__ float kst[DD * KST];
    int bh = blockIdx.x, ch = blockIdx.y;
    int t = threadIdx.x;
    for (int i = t; i < NTOP * DD; i += 256) {
        int u = i >> 6, d = i & 63;
        int l = g_top[bh * NTOP + u];
        qs[i] = g_q[((size_t)bh * LL + l) * DD + d];
    }
    int l0 = ch * 128;
    for (int i = t; i < 128 * DD; i += 256) {
        int ln = i >> 6, d = i & 63;
        kst[d * KST + ln] = g_k[((size_t)bh * LL + l0 + ln) * DD + d];
    }
    __syncthreads();
    int lane = t & 31, w = t >> 5;
    int ln0 = lane * 4;
    for (int g = 0; g < 5; g++) {
        int u = g * 8 + w;
        float4 acc = {0.f, 0.f, 0.f, 0.f};
        #pragma unroll 16
        for (int kk = 0; kk < DD; kk++) {
            float qv = qs[u * DD + kk];
            float4 kv = *(const float4*)&kst[kk * KST + ln0];
            acc.x += qv * kv.x; acc.y += qv * kv.y;
            acc.z += qv * kv.z; acc.w += qv * kv.w;
        }
        float4 es;
        es.x = expf(acc.x); es.y = expf(acc.y);
        es.z = expf(acc.z); es.w = expf(acc.w);
        *(float4*)&g_es[((size_t)(bh * NTOP + u)) * LL + l0 + ln0] = es;
    }
}

__global__ __launch_bounds__(256) void den_kernel() {
    __shared__ float sm[256];
    int r = blockIdx.x;
    const float* p = g_es + (size_t)r * LL;
    float s = 0.f;
    for (int i = threadIdx.x; i < LL; i += 256) s += p[i];
    sm[threadIdx.x] = s; __syncthreads();
    for (int st = 128; st; st >>= 1) {
        if (threadIdx.x < st) sm[threadIdx.x] += sm[threadIdx.x + st];
        __syncthreads();
    }
    if (threadIdx.x == 0) g_den[r] = sm[0];
}

__global__ __launch_bounds__(256) void pupd_kernel() {
    __shared__ float ess[NTOP * 64];
    __shared__ float vs[64 * 64];
    int bh = blockIdx.x, ch = blockIdx.y;
    int t = threadIdx.x;
    int l0 = ch * 64;
    for (int i = t; i < NTOP * 64; i += 256) {
        int u = i >> 6, l = i & 63;
        ess[i] = g_es[((size_t)(bh * NTOP + u)) * LL + l0 + l];
    }
    for (int i = t; i < 64 * 64; i += 256)
        vs[i] = g_v[((size_t)bh * LL + l0) * DD + i];
    __syncthreads();
    int d = t & 63, gq = t >> 6;
    float acc[10] = {0.f,0.f,0.f,0.f,0.f,0.f,0.f,0.f,0.f,0.f};
    for (int l = 0; l < 64; l++) {
        float vv = vs[l * 64 + d];
        #pragma unroll
        for (int j = 0; j < 10; j++) acc[j] += ess[(gq * 10 + j) * 64 + l] * vv;
    }
    #pragma unroll
    for (int j = 0; j < 10; j++) {
        int u = gq * 10 + j;
        g_pupd[(((size_t)ch * BH + bh) * NTOP + u) * DD + d] = acc[j];
    }
}

__global__ void updreduce_kernel() {
    int r = blockIdx.x;
    int d = threadIdx.x;
    float s = 0.f;
    for (int c = 0; c < PCH; c++)
        s += g_pupd[((size_t)c * BH * NTOP + r) * DD + d];
    g_upd[(size_t)r * DD + d] = s / g_den[r];
}

__global__ __launch_bounds__(256) void vmean_kernel() {
    __shared__ float sm[256];
    int bh = blockIdx.x, t = threadIdx.x;
    int d = t & 63, p = t >> 6;
    float s = 0.f;
    for (int l = p; l < LL; l += 4) s += g_v[((size_t)bh * LL + l) * DD + d];
    sm[t] = s; __syncthreads();
    if (t < 128) sm[t] += sm[t + 128];
    __syncthreads();
    if (t < 64) g_vmean[bh * DD + t] = (sm[t] + sm[t + 64]) * (1.0f / LL);
}

__global__ __launch_bounds__(128) void base_kernel(const float* __restrict__ Wo,
                                                   const float* __restrict__ bo) {
    __shared__ float cm[EE];
    int b = blockIdx.x, jc = blockIdx.y, t = threadIdx.x;
    for (int i = t; i < EE; i += 128) cm[i] = g_vmean[b * EE + i];
    __syncthreads();
    int j = jc * 128 + t;
    float acc = bo[j];
    const float* wrow = Wo + (size_t)j * EE;
    for (int e = 0; e < EE; e += 4) {
        float4 w = *(const float4*)&wrow[e];
        acc += cm[e] * w.x + cm[e+1] * w.y + cm[e+2] * w.z + cm[e+3] * w.w;
    }
    g_base[b * EE + j] = acc;
}

__global__ __launch_bounds__(256) void fill_kernel(float4* __restrict__ out4) {
    int i = blockIdx.x * 256 + threadIdx.x;
    int b  = i >> 18;
    int j4 = i & 127;
    out4[i] = *(const float4*)&g_base[b * EE + j4 * 4];
}

__global__ __launch_bounds__(512) void update_kernel(const float* __restrict__ Wo,
                                                     float* __restrict__ out) {
    __shared__ float del[DD];
    int r = blockIdx.x;
    int bh = r / NTOP;
    int b = bh >> 3, h = bh & 7;
    int t = threadIdx.x;
    if (t < DD) del[t] = g_upd[(size_t)r * DD + t] - g_vmean[bh * DD + t];
    __syncthreads();
    int l = g_top[r];
    const float* wrow = Wo + (size_t)t * EE + h * DD;
    float acc = 0.f;
    #pragma unroll
    for (int dd = 0; dd < DD; dd += 4) {
        float4 w = *(const float4*)&wrow[dd];
        acc += del[dd] * w.x + del[dd+1] * w.y + del[dd+2] * w.z + del[dd+3] * w.w;
    }
    atomicAdd(&out[((size_t)b * LL + l) * EE + t], acc);
}

extern "C" void kernel_launch(void* const* d_in, const int* in_sizes, int n_in,
                              void* d_out, int out_size) {
    const float* query = (const float*)d_in[0];
    const float* key   = (const float*)d_in[1];
    const float* value = (const float*)d_in[2];
    const int*   idxs  = (const int*)d_in[3];
    const float* Wq = (const float*)d_in[4];
    const float* bq = (const float*)d_in[5];
    const float* Wk = (const float*)d_in[6];
    const float* bk = (const float*)d_in[7];
    const float* Wv = (const float*)d_in[8];
    const float* bv = (const float*)d_in[9];
    const float* Wo = (const float*)d_in[10];
    const float* bo = (const float*)d_in[11];
    float* out = (float*)d_out;

    proj_gemm<<<dim3(64, 4, 3), 256>>>(query, key, value, Wq, Wk, Wv, bq, bk, bv);
    qk_sample_kernel<<<NROWS * HH / 8, 256>>>(idxs);          // 8192 blocks, 1 warp per (b,h,l)
    topk_kernel<<<BH, 256>>>();
    scores_kernel<<<dim3(BH, 16), 256>>>();
    den_kernel<<<BH * NTOP, 256>>>();
    pupd_kernel<<<dim3(BH, PCH), 256>>>();
    updreduce_kernel<<<BH * NTOP, 64>>>();
    vmean_kernel<<<BH, 256>>>();
    base_kernel<<<dim3(BB, 4), 128>>>(Wo, bo);
    fill_kernel<<<4096, 256>>>((float4*)out);
    update_kernel<<<BH * NTOP, 512>>>(Wo, out);
}

// round 3
// speedup vs baseline: 1.1997x; 1.1997x over previous
#include <cuda_runtime.h>
#include <cuda_bf16.h>
#include <math.h>
#include <float.h>
#include <stdint.h>

#define BB    4
#define LL    2048
#define EE    512
#define HH    8
#define DD    64
#define UU    40
#define NTOP  40
#define BH    32
#define NROWS 8192
#define PCH   32

// ---------------- scratch ----------------
__device__ float g_q[BH*LL*DD];
__device__ float g_k[BH*LL*DD];
__device__ float g_v[BH*LL*DD];
__device__ float g_M[BH*LL];
__device__ int   g_top[BH*NTOP];
__device__ float g_es[(size_t)BH*NTOP*LL];
__device__ float g_den[BH*NTOP];
__device__ float g_pupd[(size_t)PCH*BH*NTOP*DD];
__device__ float g_upd[BH*NTOP*DD];
__device__ float g_vmean[BH*DD];
__device__ float g_base[BB*EE];

// bf16 split scratch: [which q/k/v][split h/m/l]
__device__ __nv_bfloat16 g_sx[3][3][(size_t)NROWS*EE];
__device__ __nv_bfloat16 g_sw[3][3][EE*EE];

// ---------------- split: fp32 -> bf16 hi/mid/lo ----------------
__device__ __forceinline__ void split3(float x, __nv_bfloat16& h, __nv_bfloat16& m, __nv_bfloat16& l) {
    h = __float2bfloat16_rn(x);
    float r = x - __bfloat162float(h);
    m = __float2bfloat16_rn(r);
    float s = r - __bfloat162float(m);
    l = __float2bfloat16_rn(s);
}

__global__ __launch_bounds__(256) void split_kernel(
    const float* __restrict__ s0, const float* __restrict__ s1, const float* __restrict__ s2,
    int n4, int isW)
{
    int which = blockIdx.y;
    const float* src = (which == 0) ? s0 : (which == 1) ? s1 : s2;
    __nv_bfloat16* dh = isW ? g_sw[which][0] : g_sx[which][0];
    __nv_bfloat16* dm = isW ? g_sw[which][1] : g_sx[which][1];
    __nv_bfloat16* dl = isW ? g_sw[which][2] : g_sx[which][2];
    int i = blockIdx.x * 256 + threadIdx.x;
    if (i >= n4) return;
    float4 x = ((const float4*)src)[i];
    __nv_bfloat16 h[4], m[4], l[4];
    split3(x.x, h[0], m[0], l[0]);
    split3(x.y, h[1], m[1], l[1]);
    split3(x.z, h[2], m[2], l[2]);
    split3(x.w, h[3], m[3], l[3]);
    ((uint2*)dh)[i] = *(uint2*)h;
    ((uint2*)dm)[i] = *(uint2*)m;
    ((uint2*)dl)[i] = *(uint2*)l;
}

// ---------------- mma.sync projection GEMM ----------------
// out[i,j] = sum_e X[i,e]*W[j,e] + bias[j] -> (b,h,l,d) layout
// A = X splits (row-major [M,K]), B = W splits (row-major [N,K] == col-major B)
#define BM 128
#define BN 128
#define BK 32
#define SROW 40   // padded halves per SMEM row (80B: 16B-aligned, 5 coprime 8 -> ldmatrix conflict-free)

__device__ __forceinline__ uint32_t smem_u32(const void* p) {
    uint32_t a;
    asm("{ .reg .u64 t; cvta.to.shared.u64 t, %1; cvt.u32.u64 %0, t; }" : "=r"(a) : "l"(p));
    return a;
}
__device__ __forceinline__ void cpa16(uint32_t dst, const void* src) {
    asm volatile("cp.async.cg.shared.global [%0], [%1], 16;" :: "r"(dst), "l"(src));
}
__device__ __forceinline__ void ldsm_x4(uint32_t& r0, uint32_t& r1, uint32_t& r2, uint32_t& r3, uint32_t a) {
    asm volatile("ldmatrix.sync.aligned.m8n8.x4.shared.b16 {%0,%1,%2,%3}, [%4];"
        : "=r"(r0), "=r"(r1), "=r"(r2), "=r"(r3) : "r"(a));
}
__device__ __forceinline__ void ldsm_x2(uint32_t& r0, uint32_t& r1, uint32_t a) {
    asm volatile("ldmatrix.sync.aligned.m8n8.x2.shared.b16 {%0,%1}, [%2];"
        : "=r"(r0), "=r"(r1) : "r"(a));
}
__device__ __forceinline__ void mma16816(float* c, const uint32_t* a, const uint32_t* b) {
    asm volatile("mma.sync.aligned.m16n8k16.row.col.f32.bf16.bf16.f32 "
        "{%0,%1,%2,%3}, {%4,%5,%6,%7}, {%8,%9}, {%0,%1,%2,%3};"
        : "+f"(c[0]), "+f"(c[1]), "+f"(c[2]), "+f"(c[3])
        : "r"(a[0]), "r"(a[1]), "r"(a[2]), "r"(a[3]), "r"(b[0]), "r"(b[1]));
}

__constant__ int c_SA[6] = {0, 0, 1, 1, 0, 2};
__constant__ int c_SB[6] = {0, 1, 0, 1, 2, 0};

__global__ __launch_bounds__(256) void proj_mma(
    const float* __restrict__ bq, const float* __restrict__ bk, const float* __restrict__ bv)
{
    __shared__ __nv_bfloat16 sA[2][BM * SROW];
    __shared__ __nv_bfloat16 sB[2][BN * SROW];

    int z = blockIdx.z;
    int m0 = blockIdx.x * BM;
    int n0 = blockIdx.y * BN;
    int tid = threadIdx.x;
    int lane = tid & 31, wid = tid >> 5;
    int warp_m = wid & 1;        // 0..1 -> 64 rows each
    int warp_n = wid >> 1;       // 0..3 -> 32 cols each

    int nterms = (z < 2) ? 6 : 3;
    int nch = nterms * (EE / BK);

    const float* bias = (z == 0) ? bq : (z == 1) ? bk : bv;
    float* out = (z == 0) ? g_q : (z == 1) ? g_k : g_v;

    uint32_t sAu = smem_u32(sA);
    uint32_t sBu = smem_u32(sB);

    float acc[4][4][4];
    #pragma unroll
    for (int i = 0; i < 4; i++)
        #pragma unroll
        for (int j = 0; j < 4; j++)
            #pragma unroll
            for (int c = 0; c < 4; c++) acc[i][j][c] = 0.f;

    // per-thread load indices: 2 x 16B vectors for A and B each
    int vrow0 = tid >> 2,        vcc0 = tid & 3;
    int vrow1 = (tid + 256) >> 2, vcc1 = (tid + 256) & 3;

    auto issue_load = [&](int c, int buf) {
        int t = c >> 4;
        int k0 = (c & 15) * BK;
        const __nv_bfloat16* pa = g_sx[z][c_SA[t]] + (size_t)m0 * EE + k0;
        const __nv_bfloat16* pb = g_sw[z][c_SB[t]] + (size_t)n0 * EE + k0;
        uint32_t da = sAu + (uint32_t)buf * BM * SROW * 2;
        uint32_t db = sBu + (uint32_t)buf * BN * SROW * 2;
        cpa16(da + (vrow0 * SROW + vcc0 * 8) * 2, pa + (size_t)vrow0 * EE + vcc0 * 8);
        cpa16(da + (vrow1 * SROW + vcc1 * 8) * 2, pa + (size_t)vrow1 * EE + vcc1 * 8);
        cpa16(db + (vrow0 * SROW + vcc0 * 8) * 2, pb + (size_t)vrow0 * EE + vcc0 * 8);
        cpa16(db + (vrow1 * SROW + vcc1 * 8) * 2, pb + (size_t)vrow1 * EE + vcc1 * 8);
        asm volatile("cp.async.commit_group;" ::: "memory");
    };

    issue_load(0, 0);

    for (int c = 0; c < nch; c++) {
        int buf = c & 1;
        if (c + 1 < nch) {
            issue_load(c + 1, buf ^ 1);
            asm volatile("cp.async.wait_group 1;" ::: "memory");
        } else {
            asm volatile("cp.async.wait_group 0;" ::: "memory");
        }
        __syncthreads();

        uint32_t Abase = sAu + (uint32_t)buf * BM * SROW * 2;
        uint32_t Bbase = sBu + (uint32_t)buf * BN * SROW * 2;
        #pragma unroll
        for (int ks = 0; ks < 2; ks++) {
            uint32_t af[4][4], bf[4][2];
            #pragma unroll
            for (int mt = 0; mt < 4; mt++) {
                int r = warp_m * 64 + mt * 16 + (lane & 15);
                int kh = ks * 16 + (lane >> 4) * 8;
                ldsm_x4(af[mt][0], af[mt][1], af[mt][2], af[mt][3],
                        Abase + (r * SROW + kh) * 2);
            }
            #pragma unroll
            for (int nt = 0; nt < 4; nt++) {
                int r = warp_n * 32 + nt * 8 + (lane & 7);
                int kh = ks * 16 + ((lane >> 3) & 1) * 8;
                ldsm_x2(bf[nt][0], bf[nt][1], Bbase + (r * SROW + kh) * 2);
            }
            #pragma unroll
            for (int mt = 0; mt < 4; mt++)
                #pragma unroll
                for (int nt = 0; nt < 4; nt++)
                    mma16816(acc[mt][nt], af[mt], bf[nt]);
        }
        __syncthreads();
    }

    // epilogue: fragment regs -> biased scatter into (b,h,l,d)
    int gpr = lane >> 2, tg = lane & 3;
    #pragma unroll
    for (int mt = 0; mt < 4; mt++) {
        #pragma unroll
        for (int nt = 0; nt < 4; nt++) {
            int m = m0 + warp_m * 64 + mt * 16 + gpr;
            int n = n0 + warp_n * 32 + nt * 8 + tg * 2;
            float b0v = bias[n], b1v = bias[n + 1];
            int h = n >> 6, d = n & 63;
            {
                int bb = m >> 11, l = m & 2047;
                float2 o = { acc[mt][nt][0] + b0v, acc[mt][nt][1] + b1v };
                *(float2*)&out[(((size_t)bb * HH + h) * LL + l) * DD + d] = o;
            }
            {
                int m2 = m + 8;
                int bb = m2 >> 11, l = m2 & 2047;
                float2 o = { acc[mt][nt][2] + b0v, acc[mt][nt][3] + b1v };
                *(float2*)&out[(((size_t)bb * HH + h) * LL + l) * DD + d] = o;
            }
        }
    }
}

// ---------------- rest of pipeline (round-1, known-good) ----------------
__global__ __launch_bounds__(256) void qk_sample_kernel(const int* __restrict__ idxs) {
    int gw   = blockIdx.x * 8 + (threadIdx.x >> 5);
    int lane = threadIdx.x & 31;
    int bh = gw >> 11, l = gw & 2047;
    const float* qrow = g_q + ((size_t)bh * LL + l) * DD;
    float2 qv = *(const float2*)&qrow[lane * 2];
    const float* kbase = g_k + (size_t)bh * LL * DD;
    float smax = -FLT_MAX, ssum = 0.f;
    for (int s = 0; s < UU; s++) {
        int ki = idxs[l * UU + s];
        float2 kv = *(const float2*)&kbase[(size_t)ki * DD + lane * 2];
        float p = qv.x * kv.x + qv.y * kv.y;
        #pragma unroll
        for (int off = 16; off; off >>= 1) p += __shfl_xor_sync(0xffffffffu, p, off);
        smax = fmaxf(smax, p);
        ssum += p;
    }
    if (lane == 0) g_M[gw] = smax - ssum * (1.0f / LL);
}

__global__ __launch_bounds__(256) void topk_kernel() {
    __shared__ float vals[LL];
    __shared__ float rv[256];
    __shared__ int   ri[256];
    int bh = blockIdx.x, t = threadIdx.x;
    for (int i = t; i < LL; i += 256) vals[i] = g_M[bh * LL + i];
    __syncthreads();
    for (int it = 0; it < NTOP; it++) {
        float bv = -FLT_MAX; int bi = 0x7fffffff;
        for (int i = t; i < LL; i += 256) {
            float v = vals[i];
            if (v > bv || (v == bv && i < bi)) { bv = v; bi = i; }
        }
        rv[t] = bv; ri[t] = bi;
        __syncthreads();
        for (int s = 128; s > 0; s >>= 1) {
            if (t < s) {
                float ov = rv[t + s]; int oi = ri[t + s];
                if (ov > rv[t] || (ov == rv[t] && oi < ri[t])) { rv[t] = ov; ri[t] = oi; }
            }
            __syncthreads();
        }
        if (t == 0) { g_top[bh * NTOP + it] = ri[0]; vals[ri[0]] = -FLT_MAX; }
        __syncthreads();
    }
}

#define KST 132
__global__ __launch_bounds__(256) void scores_kernel() {
    __shared__ float qs[NTOP * DD];
    __shared__ float kst[DD * KST];
    int bh = blockIdx.x, ch = blockIdx.y;
    int t = threadIdx.x;
    for (int i = t; i < NTOP * DD; i += 256) {
        int u = i >> 6, d = i & 63;
        int l = g_top[bh * NTOP + u];
        qs[i] = g_q[((size_t)bh * LL + l) * DD + d];
    }
    int l0 = ch * 128;
    for (int i = t; i < 128 * DD; i += 256) {
        int ln = i >> 6, d = i & 63;
        kst[d * KST + ln] = g_k[((size_t)bh * LL + l0 + ln) * DD + d];
    }
    __syncthreads();
    int lane = t & 31, w = t >> 5;
    int ln0 = lane * 4;
    for (int g = 0; g < 5; g++) {
        int u = g * 8 + w;
        float4 acc = {0.f, 0.f, 0.f, 0.f};
        #pragma unroll 16
        for (int kk = 0; kk < DD; kk++) {
            float qv = qs[u * DD + kk];
            float4 kv = *(const float4*)&kst[kk * KST + ln0];
            acc.x += qv * kv.x; acc.y += qv * kv.y;
            acc.z += qv * kv.z; acc.w += qv * kv.w;
        }
        float4 es;
        es.x = expf(acc.x); es.y = expf(acc.y);
        es.z = expf(acc.z); es.w = expf(acc.w);
        *(float4*)&g_es[((size_t)(bh * NTOP + u)) * LL + l0 + ln0] = es;
    }
}

__global__ __launch_bounds__(256) void den_kernel() {
    __shared__ float sm[256];
    int r = blockIdx.x;
    const float* p = g_es + (size_t)r * LL;
    float s = 0.f;
    for (int i = threadIdx.x; i < LL; i += 256) s += p[i];
    sm[threadIdx.x] = s; __syncthreads();
    for (int st = 128; st; st >>= 1) {
        if (threadIdx.x < st) sm[threadIdx.x] += sm[threadIdx.x + st];
        __syncthreads();
    }
    if (threadIdx.x == 0) g_den[r] = sm[0];
}

__global__ __launch_bounds__(256) void pupd_kernel() {
    __shared__ float ess[NTOP * 64];
    __shared__ float vs[64 * 64];
    int bh = blockIdx.x, ch = blockIdx.y;
    int t = threadIdx.x;
    int l0 = ch * 64;
    for (int i = t; i < NTOP * 64; i += 256) {
        int u = i >> 6, l = i & 63;
        ess[i] = g_es[((size_t)(bh * NTOP + u)) * LL + l0 + l];
    }
    for (int i = t; i < 64 * 64; i += 256)
        vs[i] = g_v[((size_t)bh * LL + l0) * DD + i];
    __syncthreads();
    int d = t & 63, gq = t >> 6;
    float acc[10] = {0.f,0.f,0.f,0.f,0.f,0.f,0.f,0.f,0.f,0.f};
    for (int l = 0; l < 64; l++) {
        float vv = vs[l * 64 + d];
        #pragma unroll
        for (int j = 0; j < 10; j++) acc[j] += ess[(gq * 10 + j) * 64 + l] * vv;
    }
    #pragma unroll
    for (int j = 0; j < 10; j++) {
        int u = gq * 10 + j;
        g_pupd[(((size_t)ch * BH + bh) * NTOP + u) * DD + d] = acc[j];
    }
}

__global__ void updreduce_kernel() {
    int r = blockIdx.x;
    int d = threadIdx.x;
    float s = 0.f;
    for (int c = 0; c < PCH; c++)
        s += g_pupd[((size_t)c * BH * NTOP + r) * DD + d];
    g_upd[(size_t)r * DD + d] = s / g_den[r];
}

__global__ __launch_bounds__(256) void vmean_kernel() {
    __shared__ float sm[256];
    int bh = blockIdx.x, t = threadIdx.x;
    int d = t & 63, p = t >> 6;
    float s = 0.f;
    for (int l = p; l < LL; l += 4) s += g_v[((size_t)bh * LL + l) * DD + d];
    sm[t] = s; __syncthreads();
    if (t < 128) sm[t] += sm[t + 128];
    __syncthreads();
    if (t < 64) g_vmean[bh * DD + t] = (sm[t] + sm[t + 64]) * (1.0f / LL);
}

__global__ __launch_bounds__(128) void base_kernel(const float* __restrict__ Wo,
                                                   const float* __restrict__ bo) {
    __shared__ float cm[EE];
    int b = blockIdx.x, jc = blockIdx.y, t = threadIdx.x;
    for (int i = t; i < EE; i += 128) cm[i] = g_vmean[b * EE + i];
    __syncthreads();
    int j = jc * 128 + t;
    float acc = bo[j];
    const float* wrow = Wo + (size_t)j * EE;
    for (int e = 0; e < EE; e += 4) {
        float4 w = *(const float4*)&wrow[e];
        acc += cm[e] * w.x + cm[e+1] * w.y + cm[e+2] * w.z + cm[e+3] * w.w;
    }
    g_base[b * EE + j] = acc;
}

__global__ __launch_bounds__(256) void fill_kernel(float4* __restrict__ out4) {
    int i = blockIdx.x * 256 + threadIdx.x;
    int b  = i >> 18;
    int j4 = i & 127;
    out4[i] = *(const float4*)&g_base[b * EE + j4 * 4];
}

__global__ __launch_bounds__(512) void update_kernel(const float* __restrict__ Wo,
                                                     float* __restrict__ out) {
    __shared__ float del[DD];
    int r = blockIdx.x;
    int bh = r / NTOP;
    int b = bh >> 3, h = bh & 7;
    int t = threadIdx.x;
    if (t < DD) del[t] = g_upd[(size_t)r * DD + t] - g_vmean[bh * DD + t];
    __syncthreads();
    int l = g_top[r];
    const float* wrow = Wo + (size_t)t * EE + h * DD;
    float acc = 0.f;
    #pragma unroll
    for (int dd = 0; dd < DD; dd += 4) {
        float4 w = *(const float4*)&wrow[dd];
        acc += del[dd] * w.x + del[dd+1] * w.y + del[dd+2] * w.z + del[dd+3] * w.w;
    }
    atomicAdd(&out[((size_t)b * LL + l) * EE + t], acc);
}

extern "C" void kernel_launch(void* const* d_in, const int* in_sizes, int n_in,
                              void* d_out, int out_size) {
    const float* query = (const float*)d_in[0];
    const float* key   = (const float*)d_in[1];
    const float* value = (const float*)d_in[2];
    const int*   idxs  = (const int*)d_in[3];
    const float* Wq = (const float*)d_in[4];
    const float* bq = (const float*)d_in[5];
    const float* Wk = (const float*)d_in[6];
    const float* bk = (const float*)d_in[7];
    const float* Wv = (const float*)d_in[8];
    const float* bv = (const float*)d_in[9];
    const float* Wo = (const float*)d_in[10];
    const float* bo = (const float*)d_in[11];
    float* out = (float*)d_out;

    // splits: activations (4M floats each) and weights (256K floats each)
    split_kernel<<<dim3(NROWS * EE / 4 / 256, 3), 256>>>(query, key, value, NROWS * EE / 4, 0);
    split_kernel<<<dim3(EE * EE / 4 / 256, 3), 256>>>(Wq, Wk, Wv, EE * EE / 4, 1);

    proj_mma<<<dim3(NROWS / BM, EE / BN, 3), 256>>>(bq, bk, bv);

    qk_sample_kernel<<<BH * LL / 8, 256>>>(idxs);
    topk_kernel<<<BH, 256>>>();
    scores_kernel<<<dim3(BH, 16), 256>>>();
    den_kernel<<<BH * NTOP, 256>>>();
    pupd_kernel<<<dim3(BH, PCH), 256>>>();
    updreduce_kernel<<<BH * NTOP, 64>>>();
    vmean_kernel<<<BH, 256>>>();
    base_kernel<<<dim3(BB, 4), 128>>>(Wo, bo);
    fill_kernel<<<4096, 256>>>((float4*)out);
    update_kernel<<<BH * NTOP, 512>>>(Wo, out);
}